// round 8
// baseline (speedup 1.0000x reference)
#include <cuda_runtime.h>

#define NPT 16384
#define BB  2

typedef unsigned long long ull;

__device__ float g_f [BB*NPT*64];
__device__ float g_q [BB*NPT*64];     // QS = s0*q - t0
__device__ float g_kv[BB*NPT*128];    // [row][0:64]=s0*(k+pr), [64:128]=v+pr
__device__ float g_xm[BB*NPT*64];

// duplicated-pair GEMM weights: [(c_in*64 + c_out)*2 + {0,1}] both = w
__device__ float g_W1d[32*64*2];
__device__ float g_Wqd[64*64*2], g_Wkd[64*64*2], g_Wvd[64*64*2], g_W2d[64*64*2];
__device__ float g_t1[64];
__device__ float g_bqv[64], g_bkv[64], g_bvv[64];
__device__ float g_Wp1f[9], g_tp[3];
__device__ float g_Wp2b[64*4];
__device__ float g_s0t0[64*2];
// pair-interleaved Ww1: [( (c>>1)*8 + j )*2 + (c&1)] = Ww1[j][c]*sw_j
__device__ float g_Ww1i[512];
__device__ float g_tw1[8], g_Ww2m[64], g_bw2v[8];
__device__ float g_smt[64*2];
__device__ float g_t2[64];

__device__ __forceinline__ ull pk2(float lo, float hi) {
    ull r; asm("mov.b64 %0, {%1, %2};" : "=l"(r) : "f"(lo), "f"(hi)); return r;
}
__device__ __forceinline__ void upk2(ull v, float& lo, float& hi) {
    asm("mov.b64 {%0, %1}, %2;" : "=f"(lo), "=f"(hi) : "l"(v));
}
__device__ __forceinline__ void fma2(ull& d, ull a, ull b) {
    asm("fma.rn.f32x2 %0, %1, %2, %0;" : "+l"(d) : "l"(a), "l"(b));
}
__device__ __forceinline__ float lrelu(float x) { return fmaxf(x, 0.2f*x); }

// ---------------- prep ------------------------------------------------------
__global__ void k_prep(const float* __restrict__ W1,  const float* __restrict__ bn1,
                       const float* __restrict__ Wq,  const float* __restrict__ bq,
                       const float* __restrict__ Wk,  const float* __restrict__ bk,
                       const float* __restrict__ Wv,  const float* __restrict__ bv,
                       const float* __restrict__ Wp1, const float* __restrict__ bnp1,
                       const float* __restrict__ Wp2, const float* __restrict__ bp2,
                       const float* __restrict__ bnw0,const float* __restrict__ Ww1,
                       const float* __restrict__ bnw1,const float* __restrict__ Ww2,
                       const float* __restrict__ bw2, const float* __restrict__ bn_mid,
                       const float* __restrict__ W2,  const float* __restrict__ bn2)
{
    int c = blockIdx.x;   // 0..63 output channel
    int i = threadIdx.x;  // 0..63 input channel
    float s1 = bn1[c] * rsqrtf(bn1[192+c] + 1e-5f);
    float s2 = bn2[c] * rsqrtf(bn2[192+c] + 1e-5f);
    if (i < 32) {
        float w = W1[c*32+i]*s1;
        g_W1d[(i*64+c)*2+0] = w; g_W1d[(i*64+c)*2+1] = w;
    }
    {
        float wq = Wq[c*64+i], wk = Wk[c*64+i], wv = Wv[c*64+i], w2 = W2[c*64+i]*s2;
        g_Wqd[(i*64+c)*2+0] = wq; g_Wqd[(i*64+c)*2+1] = wq;
        g_Wkd[(i*64+c)*2+0] = wk; g_Wkd[(i*64+c)*2+1] = wk;
        g_Wvd[(i*64+c)*2+0] = wv; g_Wvd[(i*64+c)*2+1] = wv;
        g_W2d[(i*64+c)*2+0] = w2; g_W2d[(i*64+c)*2+1] = w2;
    }
    if (i < 8) {
        float sw = bnw1[i] * rsqrtf(bnw1[24+i] + 1e-5f);
        g_Ww1i[((c>>1)*8 + i)*2 + (c&1)] = Ww1[i*64+c]*sw;
    }
    if (i == 0) {
        g_t1[c] = bn1[64+c] - bn1[128+c]*s1;
        g_bqv[c] = bq[c]; g_bkv[c] = bk[c]; g_bvv[c] = bv[c];
        g_Wp2b[c*4+0] = Wp2[c*3+0];
        g_Wp2b[c*4+1] = Wp2[c*3+1];
        g_Wp2b[c*4+2] = Wp2[c*3+2];
        g_Wp2b[c*4+3] = bp2[c];
        float s0 = bnw0[c] * rsqrtf(bnw0[192+c] + 1e-5f);
        g_s0t0[c*2+0] = s0;
        g_s0t0[c*2+1] = bnw0[64+c] - bnw0[128+c]*s0;
        float sm = bn_mid[c] * rsqrtf(bn_mid[192+c] + 1e-5f);
        g_smt[c*2+0] = sm;
        g_smt[c*2+1] = bn_mid[64+c] - bn_mid[128+c]*sm;
        g_t2[c] = bn2[64+c] - bn2[128+c]*s2;
    }
    if (c == 0) {
        if (i < 3) {
            float sp = bnp1[i] * rsqrtf(bnp1[9+i] + 1e-5f);
            g_Wp1f[i*3+0] = Wp1[i*3+0]*sp;
            g_Wp1f[i*3+1] = Wp1[i*3+1]*sp;
            g_Wp1f[i*3+2] = Wp1[i*3+2]*sp;
            g_tp[i] = bnp1[3+i] - bnp1[6+i]*sp;
        }
        if (i < 8) {
            float sw = bnw1[i] * rsqrtf(bnw1[24+i] + 1e-5f);
            g_tw1[i]  = bnw1[8+i] - bnw1[16+i]*sw;
            g_bw2v[i] = bw2[i];
        }
        g_Ww2m[i] = Ww2[i];
    }
}

// ---------------- fused projections: f, QS, K', V' ---------------------------
__global__ void __launch_bounds__(256) k_proj(const float* __restrict__ feat,
                                              const float* __restrict__ xyz)
{
    __shared__ float sfe[32*68];
    __shared__ float sf [64*68];
    __shared__ float sh [64*4];
    int t  = threadIdx.x;
    int b  = blockIdx.y;
    int n0 = blockIdx.x * 64;
    size_t base = (size_t)b*NPT + n0;

    #pragma unroll
    for (int r = 0; r < 8; r++) {
        int li = r*256 + t;
        int i = li >> 6, p = li & 63;
        sfe[i*68+p] = feat[(size_t)(b*32 + i)*NPT + n0 + p];
    }
    if (t < 64) {
        const float* xr = xyz + (base + t)*3;
        float X = xr[0], Y = xr[1], Z = xr[2];
        sh[t*4+0] = fmaxf(fmaf(g_Wp1f[0], X, fmaf(g_Wp1f[1], Y, fmaf(g_Wp1f[2], Z, g_tp[0]))), 0.f);
        sh[t*4+1] = fmaxf(fmaf(g_Wp1f[3], X, fmaf(g_Wp1f[4], Y, fmaf(g_Wp1f[5], Z, g_tp[1]))), 0.f);
        sh[t*4+2] = fmaxf(fmaf(g_Wp1f[6], X, fmaf(g_Wp1f[7], Y, fmaf(g_Wp1f[8], Z, g_tp[2]))), 0.f);
    }
    __syncthreads();

    int cc = t & 15, pg = t >> 4;
    int cb = 4*cc, pb = 4*pg;

    float a[4][4];

    // ---- GEMM1: f = relu(W1f x + t1)
    {
        ull acc[4][2];
        #pragma unroll
        for (int ch = 0; ch < 4; ch++) { acc[ch][0] = 0ull; acc[ch][1] = 0ull; }
        #pragma unroll 8
        for (int i = 0; i < 32; i++) {
            ulonglong2 fp = *(const ulonglong2*)&sfe[i*68 + pb];
            ulonglong2 wA = *(const ulonglong2*)&g_W1d[(i*64 + cb)*2];
            ulonglong2 wB = *(const ulonglong2*)&g_W1d[(i*64 + cb + 2)*2];
            fma2(acc[0][0], wA.x, fp.x); fma2(acc[0][1], wA.x, fp.y);
            fma2(acc[1][0], wA.y, fp.x); fma2(acc[1][1], wA.y, fp.y);
            fma2(acc[2][0], wB.x, fp.x); fma2(acc[2][1], wB.x, fp.y);
            fma2(acc[3][0], wB.y, fp.x); fma2(acc[3][1], wB.y, fp.y);
        }
        float4 t1v = *(const float4*)&g_t1[cb];
        float tb[4] = {t1v.x, t1v.y, t1v.z, t1v.w};
        #pragma unroll
        for (int ch = 0; ch < 4; ch++) {
            upk2(acc[ch][0], a[ch][0], a[ch][1]);
            upk2(acc[ch][1], a[ch][2], a[ch][3]);
            #pragma unroll
            for (int pp = 0; pp < 4; pp++) {
                a[ch][pp] = fmaxf(a[ch][pp] + tb[ch], 0.f);
                sf[(cb+ch)*68 + pb + pp] = a[ch][pp];
            }
        }
        #pragma unroll
        for (int pp = 0; pp < 4; pp++)
            *(float4*)&g_f[(base + pb + pp)*64 + cb] =
                make_float4(a[0][pp], a[1][pp], a[2][pp], a[3][pp]);
    }
    __syncthreads();

    // ---- GEMM q -> QS, GEMM k -> K', GEMM v -> V'
    #pragma unroll
    for (int z = 0; z < 3; z++) {
        const float* Wd   = (z == 0) ? g_Wqd : (z == 1) ? g_Wkd : g_Wvd;
        const float* bias = (z == 0) ? g_bqv : (z == 1) ? g_bkv : g_bvv;
        ull acc[4][2];
        #pragma unroll
        for (int ch = 0; ch < 4; ch++) { acc[ch][0] = 0ull; acc[ch][1] = 0ull; }
        #pragma unroll 8
        for (int c = 0; c < 64; c++) {
            ulonglong2 fp = *(const ulonglong2*)&sf[c*68 + pb];
            ulonglong2 wA = *(const ulonglong2*)&Wd[(c*64 + cb)*2];
            ulonglong2 wB = *(const ulonglong2*)&Wd[(c*64 + cb + 2)*2];
            fma2(acc[0][0], wA.x, fp.x); fma2(acc[0][1], wA.x, fp.y);
            fma2(acc[1][0], wA.y, fp.x); fma2(acc[1][1], wA.y, fp.y);
            fma2(acc[2][0], wB.x, fp.x); fma2(acc[2][1], wB.x, fp.y);
            fma2(acc[3][0], wB.y, fp.x); fma2(acc[3][1], wB.y, fp.y);
        }
        #pragma unroll
        for (int ch = 0; ch < 4; ch++) {
            upk2(acc[ch][0], a[ch][0], a[ch][1]);
            upk2(acc[ch][1], a[ch][2], a[ch][3]);
        }
        float4 bb = *(const float4*)&bias[cb];
        float bvr[4] = {bb.x, bb.y, bb.z, bb.w};
        if (z == 0) {
            #pragma unroll
            for (int pp = 0; pp < 4; pp++) {
                float o[4];
                #pragma unroll
                for (int ch = 0; ch < 4; ch++) {
                    float2 st = *(const float2*)&g_s0t0[(cb+ch)*2];
                    o[ch] = fmaf(st.x, a[ch][pp] + bvr[ch], -st.y);
                }
                *(float4*)&g_q[(base + pb + pp)*64 + cb] =
                    make_float4(o[0], o[1], o[2], o[3]);
            }
        } else {
            float* dst = (z == 1) ? g_kv : (g_kv + 64);
            #pragma unroll
            for (int pp = 0; pp < 4; pp++) {
                float h0 = sh[(pb+pp)*4+0], h1 = sh[(pb+pp)*4+1], h2 = sh[(pb+pp)*4+2];
                float o[4];
                #pragma unroll
                for (int ch = 0; ch < 4; ch++) {
                    float4 wp = *(const float4*)&g_Wp2b[(cb+ch)*4];
                    float pr = fmaf(wp.x, h0, fmaf(wp.y, h1, fmaf(wp.z, h2, wp.w)));
                    float val = a[ch][pp] + bvr[ch] + pr;
                    if (z == 1) val *= g_s0t0[(cb+ch)*2];
                    o[ch] = val;
                }
                *(float4*)&dst[(base + pb + pp)*128 + cb] =
                    make_float4(o[0], o[1], o[2], o[3]);
            }
        }
    }
}

// ---------------- attention core: writes xm (point-major) -------------------
#define WPB 4
__global__ void __launch_bounds__(128) k_attn(const int* __restrict__ nidx)
{
    __shared__ float skv[WPB][16*64];   // K' only: 16 rows x 256B, swizzled
    __shared__ float swt[WPB][132];
    __shared__ float sWw1i[512];
    __shared__ float sWw2[64];
    __shared__ float sAux[16];

    int t = threadIdx.x;
    sWw1i[t]       = g_Ww1i[t];
    sWw1i[128+t]   = g_Ww1i[128+t];
    sWw1i[256+t]   = g_Ww1i[256+t];
    sWw1i[384+t]   = g_Ww1i[384+t];
    if (t < 64)    sWw2[t] = g_Ww2m[t];
    if (t < 8)   { sAux[t] = g_tw1[t]; sAux[8+t] = g_bw2v[t]; }
    __syncthreads();

    int warp = t >> 5, l = t & 31;
    int pid = blockIdx.x * WPB + warp;
    int b   = pid >> 14;
    int n   = pid & 16383;
    size_t rowb  = (size_t)b * NPT;
    size_t pbase = (rowb + n) * 64;

    int k = l & 15, h = l >> 4;
    int c0 = 32 * h;

    const int* nrow = nidx + (size_t)pid*16;
    int myidx = (l < 16) ? __ldg(nrow + l) : 0;

    // cooperative gather of K' (two rows per instruction), swizzled STS
    float* skvw = skv[warp];
    int i2 = l >> 4, ch16 = l & 15;
    #pragma unroll
    for (int i = 0; i < 8; i++) {
        int row = 2*i + i2;
        int r = __shfl_sync(0xffffffffu, myidx, row);
        float4 val = __ldg((const float4*)(g_kv + (rowb + r)*128) + ch16);
        int pp = ch16 ^ (row & 7);
        *(float4*)&skvw[row*64 + pp*4] = val;
    }
    __syncwarp();

    // phase 1: u = lrelu(K' - QS); packed Ww1 accumulation (even/odd channel lanes)
    ull w1a[8];
    #pragma unroll
    for (int j = 0; j < 8; j++) w1a[j] = 0ull;

    int sw8 = k & 7;
    #pragma unroll
    for (int s = 0; s < 8; s++) {
        int c = c0 + 4*s;
        float4 kk = *(const float4*)&skvw[k*64 + ((h*8 + s) ^ sw8)*4];
        float4 qs = __ldg((const float4*)(g_q + pbase + c));
        float u0 = lrelu(kk.x - qs.x);
        float u1 = lrelu(kk.y - qs.y);
        float u2 = lrelu(kk.z - qs.z);
        float u3 = lrelu(kk.w - qs.w);
        ull up0 = pk2(u0, u1);
        ull up1 = pk2(u2, u3);
        int c2 = c >> 1;  // first channel-pair index
        {
            const float* wbp = &sWw1i[c2*16];
            ulonglong2 A = *(const ulonglong2*)&wbp[0];
            ulonglong2 Bq = *(const ulonglong2*)&wbp[4];
            ulonglong2 C = *(const ulonglong2*)&wbp[8];
            ulonglong2 D = *(const ulonglong2*)&wbp[12];
            fma2(w1a[0], A.x,  up0); fma2(w1a[1], A.y,  up0);
            fma2(w1a[2], Bq.x, up0); fma2(w1a[3], Bq.y, up0);
            fma2(w1a[4], C.x,  up0); fma2(w1a[5], C.y,  up0);
            fma2(w1a[6], D.x,  up0); fma2(w1a[7], D.y,  up0);
        }
        {
            const float* wbp = &sWw1i[(c2+1)*16];
            ulonglong2 A = *(const ulonglong2*)&wbp[0];
            ulonglong2 Bq = *(const ulonglong2*)&wbp[4];
            ulonglong2 C = *(const ulonglong2*)&wbp[8];
            ulonglong2 D = *(const ulonglong2*)&wbp[12];
            fma2(w1a[0], A.x,  up1); fma2(w1a[1], A.y,  up1);
            fma2(w1a[2], Bq.x, up1); fma2(w1a[3], Bq.y, up1);
            fma2(w1a[4], C.x,  up1); fma2(w1a[5], C.y,  up1);
            fma2(w1a[6], D.x,  up1); fma2(w1a[7], D.y,  up1);
        }
    }

    float w1p[8];
    #pragma unroll
    for (int j = 0; j < 8; j++) {
        float lo, hi; upk2(w1a[j], lo, hi);
        w1p[j] = lo + hi;
    }
    #pragma unroll
    for (int j = 0; j < 8; j++)
        w1p[j] += __shfl_xor_sync(0xffffffffu, w1p[j], 16);

    float w1v[8];
    #pragma unroll
    for (int j = 0; j < 8; j++) w1v[j] = fmaxf(w1p[j] + sAux[j], 0.f);

    float wt[4];
    #pragma unroll
    for (int jj = 0; jj < 4; jj++) {
        int j = 4*h + jj;
        float a = sAux[8+j];
        #pragma unroll
        for (int i = 0; i < 8; i++) a = fmaf(sWw2[j*8+i], w1v[i], a);
        wt[jj] = a;
    }
    *(float4*)&swt[warp][k*8 + 4*h] = make_float4(wt[0], wt[1], wt[2], wt[3]);
    __syncwarp();

    // softmax over K
    {
        int j = l >> 2, kq = l & 3;
        float v0 = swt[warp][(4*kq+0)*8 + j];
        float v1 = swt[warp][(4*kq+1)*8 + j];
        float v2 = swt[warp][(4*kq+2)*8 + j];
        float v3 = swt[warp][(4*kq+3)*8 + j];
        float mx = fmaxf(fmaxf(v0, v1), fmaxf(v2, v3));
        mx = fmaxf(mx, __shfl_xor_sync(0xffffffffu, mx, 1));
        mx = fmaxf(mx, __shfl_xor_sync(0xffffffffu, mx, 2));
        float e0 = __expf(v0 - mx), e1 = __expf(v1 - mx);
        float e2 = __expf(v2 - mx), e3 = __expf(v3 - mx);
        float sm = e0 + e1 + e2 + e3;
        sm += __shfl_xor_sync(0xffffffffu, sm, 1);
        sm += __shfl_xor_sync(0xffffffffu, sm, 2);
        float inv = __fdividef(1.f, sm);
        swt[warp][(4*kq+0)*8 + j] = e0 * inv;
        swt[warp][(4*kq+1)*8 + j] = e1 * inv;
        swt[warp][(4*kq+2)*8 + j] = e2 * inv;
        swt[warp][(4*kq+3)*8 + j] = e3 * inv;
    }
    __syncwarp();

    // phase 3: lane owns channels 2l, 2l+1; packed weighted V' sum
    int cc0 = 2*l;
    int j0 = cc0 & 7;
    ull acc2 = 0ull;
    #pragma unroll
    for (int kk2 = 0; kk2 < 16; kk2++) {
        ull wv = *(const ull*)&swt[warp][kk2*8 + j0];
        int r = __shfl_sync(0xffffffffu, myidx, kk2);
        ull vv = __ldg((const ull*)(g_kv + (rowb + r)*128 + 64 + cc0));
        fma2(acc2, wv, vv);
    }
    float acc0, acc1;
    upk2(acc2, acc0, acc1);

    float4 sm4 = *(const float4*)(g_smt + 4*l);
    float xa = lrelu(fmaf(sm4.x, acc0, sm4.y));
    float xb = lrelu(fmaf(sm4.z, acc1, sm4.w));
    *(float2*)&g_xm[pbase + cc0] = make_float2(xa, xb);
}

// ---------------- conv2 + residual + lrelu, tiled GEMM -----------------------
__global__ void __launch_bounds__(256) k_out(float* __restrict__ out)
{
    __shared__ float sbuf[64*68];
    int t  = threadIdx.x;
    int b  = blockIdx.y;
    int n0 = blockIdx.x * 64;
    size_t base = (size_t)b*NPT + n0;

    int p = t & 63, chunk = t >> 6;
    #pragma unroll
    for (int j = 0; j < 4; j++) {
        int ch = chunk*16 + 4*j;
        float4 v = *(const float4*)&g_xm[(base + p)*64 + ch];
        sbuf[(ch+0)*68+p] = v.x;
        sbuf[(ch+1)*68+p] = v.y;
        sbuf[(ch+2)*68+p] = v.z;
        sbuf[(ch+3)*68+p] = v.w;
    }
    __syncthreads();

    int cc = t & 15, pg = t >> 4;
    int cb = 4*cc, pb = 4*pg;

    ull acc[4][2];
    #pragma unroll
    for (int ch = 0; ch < 4; ch++) { acc[ch][0] = 0ull; acc[ch][1] = 0ull; }

    #pragma unroll 8
    for (int c = 0; c < 64; c++) {
        ulonglong2 fp = *(const ulonglong2*)&sbuf[c*68 + pb];
        ulonglong2 wA = *(const ulonglong2*)&g_W2d[(c*64 + cb)*2];
        ulonglong2 wB = *(const ulonglong2*)&g_W2d[(c*64 + cb + 2)*2];
        fma2(acc[0][0], wA.x, fp.x); fma2(acc[0][1], wA.x, fp.y);
        fma2(acc[1][0], wA.y, fp.x); fma2(acc[1][1], wA.y, fp.y);
        fma2(acc[2][0], wB.x, fp.x); fma2(acc[2][1], wB.x, fp.y);
        fma2(acc[3][0], wB.y, fp.x); fma2(acc[3][1], wB.y, fp.y);
    }
    float a[4][4];
    #pragma unroll
    for (int ch = 0; ch < 4; ch++) {
        upk2(acc[ch][0], a[ch][0], a[ch][1]);
        upk2(acc[ch][1], a[ch][2], a[ch][3]);
    }
    __syncthreads();   // done reading sbuf, reuse as output stage

    float4 t2v = *(const float4*)&g_t2[cb];
    float tb[4] = {t2v.x, t2v.y, t2v.z, t2v.w};
    #pragma unroll
    for (int pp = 0; pp < 4; pp++) {
        float4 fv = *(const float4*)&g_f[(base + pb + pp)*64 + cb];
        float fr[4] = {fv.x, fv.y, fv.z, fv.w};
        #pragma unroll
        for (int ch = 0; ch < 4; ch++)
            sbuf[(cb+ch)*68 + pb + pp] = lrelu(a[ch][pp] + tb[ch] + fr[ch]);
    }
    __syncthreads();

    int cO = t >> 2, q = t & 3;
    #pragma unroll
    for (int i = 0; i < 4; i++) {
        float4 vq = *(const float4*)&sbuf[cO*68 + q*16 + 4*i];
        *(float4*)&out[((size_t)(b*64 + cO))*NPT + n0 + q*16 + 4*i] = vq;
    }
}

extern "C" void kernel_launch(void* const* d_in, const int* in_sizes, int n_in,
                              void* d_out, int out_size)
{
    const float* feature = (const float*)d_in[0];
    const float* xyz     = (const float*)d_in[1];
    const float* W1      = (const float*)d_in[2];
    const float* bn1     = (const float*)d_in[3];
    const float* Wq      = (const float*)d_in[4];
    const float* bq      = (const float*)d_in[5];
    const float* Wk      = (const float*)d_in[6];
    const float* bk      = (const float*)d_in[7];
    const float* Wv      = (const float*)d_in[8];
    const float* bv      = (const float*)d_in[9];
    const float* Wp1     = (const float*)d_in[10];
    const float* bnp1    = (const float*)d_in[11];
    const float* Wp2     = (const float*)d_in[12];
    const float* bp2     = (const float*)d_in[13];
    const float* bnw0    = (const float*)d_in[14];
    const float* Ww1     = (const float*)d_in[15];
    const float* bnw1    = (const float*)d_in[16];
    const float* Ww2     = (const float*)d_in[17];
    const float* bw2     = (const float*)d_in[18];
    const float* bn_mid  = (const float*)d_in[19];
    const float* W2      = (const float*)d_in[20];
    const float* bn2     = (const float*)d_in[21];
    const int*   nidx    = (const int*)d_in[22];
    float* out = (float*)d_out;

    k_prep<<<64, 64>>>(W1, bn1, Wq, bq, Wk, bk, Wv, bv, Wp1, bnp1, Wp2, bp2,
                       bnw0, Ww1, bnw1, Ww2, bw2, bn_mid, W2, bn2);
    dim3 gf(NPT/64, BB);
    k_proj<<<gf, 256>>>(feature, xyz);
    k_attn<<<(BB*NPT)/WPB, 128>>>(nidx);
    k_out<<<gf, 256>>>(out);
}

// round 9
// speedup vs baseline: 1.8293x; 1.8293x over previous
#include <cuda_runtime.h>

#define NPT 16384
#define BB  2

__device__ float g_f [BB*NPT*64];
__device__ float g_q [BB*NPT*64];     // QS = s0*q - t0
__device__ float g_kv[BB*NPT*128];    // [row][0:64]=s0*(k+pr), [64:128]=v+pr
__device__ float g_xm[BB*NPT*64];

__device__ float g_W1f[32*64];
__device__ float g_t1[64];
__device__ float g_WqT[64*64], g_WkT[64*64], g_WvT[64*64];
__device__ float g_bqv[64], g_bkv[64], g_bvv[64];
__device__ float g_Wp1f[9], g_tp[3];
__device__ float g_Wp2b[64*4];
__device__ float g_s0t0[64*2];
__device__ float g_Ww1f[64*8];
__device__ float g_tw1[8], g_Ww2m[64], g_bw2v[8];
__device__ float g_smt[64*2];
__device__ float g_W2T[64*64], g_t2[64];

__device__ __forceinline__ float lrelu(float x) { return fmaxf(x, 0.2f*x); }

// ---------------- prep: 64 blocks x 64 threads ------------------------------
__global__ void k_prep(const float* __restrict__ W1,  const float* __restrict__ bn1,
                       const float* __restrict__ Wq,  const float* __restrict__ bq,
                       const float* __restrict__ Wk,  const float* __restrict__ bk,
                       const float* __restrict__ Wv,  const float* __restrict__ bv,
                       const float* __restrict__ Wp1, const float* __restrict__ bnp1,
                       const float* __restrict__ Wp2, const float* __restrict__ bp2,
                       const float* __restrict__ bnw0,const float* __restrict__ Ww1,
                       const float* __restrict__ bnw1,const float* __restrict__ Ww2,
                       const float* __restrict__ bw2, const float* __restrict__ bn_mid,
                       const float* __restrict__ W2,  const float* __restrict__ bn2)
{
    int c = blockIdx.x;   // 0..63 output channel
    int i = threadIdx.x;  // 0..63 input channel
    float s1 = bn1[c] * rsqrtf(bn1[192+c] + 1e-5f);
    float s2 = bn2[c] * rsqrtf(bn2[192+c] + 1e-5f);
    if (i < 32) g_W1f[i*64+c] = W1[c*32+i]*s1;
    g_WqT[i*64+c] = Wq[c*64+i];
    g_WkT[i*64+c] = Wk[c*64+i];
    g_WvT[i*64+c] = Wv[c*64+i];
    g_W2T[i*64+c] = W2[c*64+i]*s2;
    if (i < 8) {
        float sw = bnw1[i] * rsqrtf(bnw1[24+i] + 1e-5f);
        g_Ww1f[c*8+i] = Ww1[i*64+c]*sw;
    }
    if (i == 0) {
        g_t1[c] = bn1[64+c] - bn1[128+c]*s1;
        g_bqv[c] = bq[c]; g_bkv[c] = bk[c]; g_bvv[c] = bv[c];
        g_Wp2b[c*4+0] = Wp2[c*3+0];
        g_Wp2b[c*4+1] = Wp2[c*3+1];
        g_Wp2b[c*4+2] = Wp2[c*3+2];
        g_Wp2b[c*4+3] = bp2[c];
        float s0 = bnw0[c] * rsqrtf(bnw0[192+c] + 1e-5f);
        g_s0t0[c*2+0] = s0;
        g_s0t0[c*2+1] = bnw0[64+c] - bnw0[128+c]*s0;
        float sm = bn_mid[c] * rsqrtf(bn_mid[192+c] + 1e-5f);
        g_smt[c*2+0] = sm;
        g_smt[c*2+1] = bn_mid[64+c] - bn_mid[128+c]*sm;
        g_t2[c] = bn2[64+c] - bn2[128+c]*s2;
    }
    if (c == 0) {
        if (i < 3) {
            float sp = bnp1[i] * rsqrtf(bnp1[9+i] + 1e-5f);
            g_Wp1f[i*3+0] = Wp1[i*3+0]*sp;
            g_Wp1f[i*3+1] = Wp1[i*3+1]*sp;
            g_Wp1f[i*3+2] = Wp1[i*3+2]*sp;
            g_tp[i] = bnp1[3+i] - bnp1[6+i]*sp;
        }
        if (i < 8) {
            float sw = bnw1[i] * rsqrtf(bnw1[24+i] + 1e-5f);
            g_tw1[i]  = bnw1[8+i] - bnw1[16+i]*sw;
            g_bw2v[i] = bw2[i];
        }
        g_Ww2m[i] = Ww2[i];
    }
}

// ---------------- fused projections: f, QS, K', V' (scalar float4 GEMMs) ----
__global__ void __launch_bounds__(256) k_proj(const float* __restrict__ feat,
                                              const float* __restrict__ xyz)
{
    __shared__ float sfe[32*68];
    __shared__ float sf [64*68];   // f tile, [c][p]
    __shared__ float sh [64*4];    // pos-MLP hidden per point
    int t  = threadIdx.x;
    int b  = blockIdx.y;
    int n0 = blockIdx.x * 64;
    size_t base = (size_t)b*NPT + n0;

    #pragma unroll
    for (int r = 0; r < 8; r++) {
        int li = r*256 + t;
        int i = li >> 6, p = li & 63;
        sfe[i*68+p] = feat[(size_t)(b*32 + i)*NPT + n0 + p];
    }
    if (t < 64) {
        const float* xr = xyz + (base + t)*3;
        float X = xr[0], Y = xr[1], Z = xr[2];
        sh[t*4+0] = fmaxf(fmaf(g_Wp1f[0], X, fmaf(g_Wp1f[1], Y, fmaf(g_Wp1f[2], Z, g_tp[0]))), 0.f);
        sh[t*4+1] = fmaxf(fmaf(g_Wp1f[3], X, fmaf(g_Wp1f[4], Y, fmaf(g_Wp1f[5], Z, g_tp[1]))), 0.f);
        sh[t*4+2] = fmaxf(fmaf(g_Wp1f[6], X, fmaf(g_Wp1f[7], Y, fmaf(g_Wp1f[8], Z, g_tp[2]))), 0.f);
    }
    __syncthreads();

    int cc = t & 15, pg = t >> 4;
    int cb = 4*cc, pb = 4*pg;

    // ---- GEMM1: f = relu(W1f x + t1); write g_f and sf
    {
        float af[4][4];
        #pragma unroll
        for (int x = 0; x < 4; x++)
            #pragma unroll
            for (int y = 0; y < 4; y++) af[x][y] = 0.f;

        #pragma unroll
        for (int i = 0; i < 32; i++) {
            float4 w  = *(const float4*)&g_W1f[i*64 + cb];
            float4 fv = *(const float4*)&sfe[i*68 + pb];
            float wc[4] = {w.x,w.y,w.z,w.w};
            float fp[4] = {fv.x,fv.y,fv.z,fv.w};
            #pragma unroll
            for (int ch = 0; ch < 4; ch++)
                #pragma unroll
                for (int pp = 0; pp < 4; pp++)
                    af[ch][pp] = fmaf(wc[ch], fp[pp], af[ch][pp]);
        }
        float4 t1v = *(const float4*)&g_t1[cb];
        float tb[4] = {t1v.x, t1v.y, t1v.z, t1v.w};
        #pragma unroll
        for (int ch = 0; ch < 4; ch++)
            #pragma unroll
            for (int pp = 0; pp < 4; pp++) {
                float v = fmaxf(af[ch][pp] + tb[ch], 0.f);
                af[ch][pp] = v;
                sf[(cb+ch)*68 + pb + pp] = v;
            }
        #pragma unroll
        for (int pp = 0; pp < 4; pp++)
            *(float4*)&g_f[(base + pb + pp)*64 + cb] =
                make_float4(af[0][pp], af[1][pp], af[2][pp], af[3][pp]);
    }
    __syncthreads();

    // ---- projections: z=0 QS, z=1 K', z=2 V'
    #pragma unroll
    for (int z = 0; z < 3; z++) {
        const float* W    = (z == 0) ? g_WqT : (z == 1) ? g_WkT : g_WvT;
        const float* bias = (z == 0) ? g_bqv : (z == 1) ? g_bkv : g_bvv;

        float a[4][4];
        #pragma unroll
        for (int x = 0; x < 4; x++)
            #pragma unroll
            for (int y = 0; y < 4; y++) a[x][y] = 0.f;

        #pragma unroll 8
        for (int c = 0; c < 64; c++) {
            float4 w  = *(const float4*)&W[c*64 + cb];
            float4 fv = *(const float4*)&sf[c*68 + pb];
            float wc[4] = {w.x,w.y,w.z,w.w};
            float fp[4] = {fv.x,fv.y,fv.z,fv.w};
            #pragma unroll
            for (int ch = 0; ch < 4; ch++)
                #pragma unroll
                for (int pp = 0; pp < 4; pp++)
                    a[ch][pp] = fmaf(wc[ch], fp[pp], a[ch][pp]);
        }
        float4 bb = *(const float4*)&bias[cb];
        float bvr[4] = {bb.x, bb.y, bb.z, bb.w};

        if (z == 0) {
            #pragma unroll
            for (int pp = 0; pp < 4; pp++) {
                float o[4];
                #pragma unroll
                for (int ch = 0; ch < 4; ch++) {
                    float2 st = *(const float2*)&g_s0t0[(cb+ch)*2];
                    o[ch] = fmaf(st.x, a[ch][pp] + bvr[ch], -st.y);
                }
                *(float4*)&g_q[(base + pb + pp)*64 + cb] =
                    make_float4(o[0], o[1], o[2], o[3]);
            }
        } else {
            float* dst = (z == 1) ? g_kv : (g_kv + 64);
            #pragma unroll
            for (int pp = 0; pp < 4; pp++) {
                float h0 = sh[(pb+pp)*4+0], h1 = sh[(pb+pp)*4+1], h2 = sh[(pb+pp)*4+2];
                float o[4];
                #pragma unroll
                for (int ch = 0; ch < 4; ch++) {
                    float4 wp = *(const float4*)&g_Wp2b[(cb+ch)*4];
                    float pr = fmaf(wp.x, h0, fmaf(wp.y, h1, fmaf(wp.z, h2, wp.w)));
                    float val = a[ch][pp] + bvr[ch] + pr;
                    if (z == 1) val *= g_s0t0[(cb+ch)*2];
                    o[ch] = val;
                }
                *(float4*)&dst[(base + pb + pp)*128 + cb] =
                    make_float4(o[0], o[1], o[2], o[3]);
            }
        }
    }
}

// ---------------- attention core: writes xm (point-major) -------------------
#define WPB 4
__global__ void __launch_bounds__(128) k_attn(const int* __restrict__ nidx)
{
    __shared__ float skv[WPB][16*64];   // K' only: 16 rows x 256B, swizzled
    __shared__ float swt[WPB][132];
    __shared__ float sWw1f[512];
    __shared__ float sWw2[64];
    __shared__ float sAux[16];

    int t = threadIdx.x;
    sWw1f[t]       = g_Ww1f[t];
    sWw1f[128+t]   = g_Ww1f[128+t];
    sWw1f[256+t]   = g_Ww1f[256+t];
    sWw1f[384+t]   = g_Ww1f[384+t];
    if (t < 64)    sWw2[t] = g_Ww2m[t];
    if (t < 8)   { sAux[t] = g_tw1[t]; sAux[8+t] = g_bw2v[t]; }
    __syncthreads();

    int warp = t >> 5, l = t & 31;
    int pid = blockIdx.x * WPB + warp;
    int b   = pid >> 14;
    int n   = pid & 16383;
    size_t rowb  = (size_t)b * NPT;
    size_t pbase = (rowb + n) * 64;

    int k = l & 15, h = l >> 4;
    int c0 = 32 * h;

    const int* nrow = nidx + (size_t)pid*16;
    int myidx = (l < 16) ? __ldg(nrow + l) : 0;

    // cooperative gather of K' (two rows per instruction), swizzled STS
    float* skvw = skv[warp];
    int i2 = l >> 4, ch16 = l & 15;
    #pragma unroll
    for (int i = 0; i < 8; i++) {
        int row = 2*i + i2;
        int r = __shfl_sync(0xffffffffu, myidx, row);
        float4 val = __ldg((const float4*)(g_kv + (rowb + r)*128) + ch16);
        int pp = ch16 ^ (row & 7);
        *(float4*)&skvw[row*64 + pp*4] = val;
    }
    __syncwarp();

    // phase 1: u = lrelu(K' - QS), accumulate Ww1 partials over own 32 channels
    float w1p[8];
    #pragma unroll
    for (int j = 0; j < 8; j++) w1p[j] = 0.f;

    int sw8 = k & 7;
    #pragma unroll
    for (int s = 0; s < 8; s++) {
        int c = c0 + 4*s;
        float4 kk = *(const float4*)&skvw[k*64 + ((h*8 + s) ^ sw8)*4];
        float4 qs = __ldg((const float4*)(g_q + pbase + c));
        float kr[4] = {kk.x,kk.y,kk.z,kk.w};
        float qr[4] = {qs.x,qs.y,qs.z,qs.w};
        #pragma unroll
        for (int e = 0; e < 4; e++) {
            int ch = c + e;
            float u = lrelu(kr[e] - qr[e]);
            float4 wA = *(const float4*)(sWw1f + ch*8);
            float4 wB = *(const float4*)(sWw1f + ch*8 + 4);
            w1p[0] = fmaf(wA.x, u, w1p[0]); w1p[1] = fmaf(wA.y, u, w1p[1]);
            w1p[2] = fmaf(wA.z, u, w1p[2]); w1p[3] = fmaf(wA.w, u, w1p[3]);
            w1p[4] = fmaf(wB.x, u, w1p[4]); w1p[5] = fmaf(wB.y, u, w1p[5]);
            w1p[6] = fmaf(wB.z, u, w1p[6]); w1p[7] = fmaf(wB.w, u, w1p[7]);
        }
    }

    #pragma unroll
    for (int j = 0; j < 8; j++)
        w1p[j] += __shfl_xor_sync(0xffffffffu, w1p[j], 16);

    float w1v[8];
    #pragma unroll
    for (int j = 0; j < 8; j++) w1v[j] = fmaxf(w1p[j] + sAux[j], 0.f);

    float wt[4];
    #pragma unroll
    for (int jj = 0; jj < 4; jj++) {
        int j = 4*h + jj;
        float a = sAux[8+j];
        #pragma unroll
        for (int i = 0; i < 8; i++) a = fmaf(sWw2[j*8+i], w1v[i], a);
        wt[jj] = a;
    }
    *(float4*)&swt[warp][k*8 + 4*h] = make_float4(wt[0], wt[1], wt[2], wt[3]);
    __syncwarp();

    // softmax over K
    {
        int j = l >> 2, kq = l & 3;
        float v0 = swt[warp][(4*kq+0)*8 + j];
        float v1 = swt[warp][(4*kq+1)*8 + j];
        float v2 = swt[warp][(4*kq+2)*8 + j];
        float v3 = swt[warp][(4*kq+3)*8 + j];
        float mx = fmaxf(fmaxf(v0, v1), fmaxf(v2, v3));
        mx = fmaxf(mx, __shfl_xor_sync(0xffffffffu, mx, 1));
        mx = fmaxf(mx, __shfl_xor_sync(0xffffffffu, mx, 2));
        float e0 = __expf(v0 - mx), e1 = __expf(v1 - mx);
        float e2 = __expf(v2 - mx), e3 = __expf(v3 - mx);
        float sm = e0 + e1 + e2 + e3;
        sm += __shfl_xor_sync(0xffffffffu, sm, 1);
        sm += __shfl_xor_sync(0xffffffffu, sm, 2);
        float inv = __fdividef(1.f, sm);
        swt[warp][(4*kq+0)*8 + j] = e0 * inv;
        swt[warp][(4*kq+1)*8 + j] = e1 * inv;
        swt[warp][(4*kq+2)*8 + j] = e2 * inv;
        swt[warp][(4*kq+3)*8 + j] = e3 * inv;
    }
    __syncwarp();

    // phase 3: lane owns channels 2l, 2l+1; V' read from global (L2-hot)
    int cc0 = 2*l;
    int j0 = cc0 & 7;
    float acc0 = 0.f, acc1 = 0.f;
    #pragma unroll
    for (int kk2 = 0; kk2 < 16; kk2++) {
        float2 wv = *(const float2*)&swt[warp][kk2*8 + j0];
        int r = __shfl_sync(0xffffffffu, myidx, kk2);
        float2 vv = __ldg((const float2*)(g_kv + (rowb + r)*128 + 64 + cc0));
        acc0 = fmaf(wv.x, vv.x, acc0);
        acc1 = fmaf(wv.y, vv.y, acc1);
    }

    float4 sm4 = *(const float4*)(g_smt + 4*l);
    float xa = lrelu(fmaf(sm4.x, acc0, sm4.y));
    float xb = lrelu(fmaf(sm4.z, acc1, sm4.w));
    *(float2*)&g_xm[pbase + cc0] = make_float2(xa, xb);
}

// ---------------- conv2 + residual + lrelu, tiled GEMM -----------------------
__global__ void __launch_bounds__(256) k_out(float* __restrict__ out)
{
    __shared__ float sbuf[64*68];
    int t  = threadIdx.x;
    int b  = blockIdx.y;
    int n0 = blockIdx.x * 64;
    size_t base = (size_t)b*NPT + n0;

    int p = t & 63, chunk = t >> 6;
    #pragma unroll
    for (int j = 0; j < 4; j++) {
        int ch = chunk*16 + 4*j;
        float4 v = *(const float4*)&g_xm[(base + p)*64 + ch];
        sbuf[(ch+0)*68+p] = v.x;
        sbuf[(ch+1)*68+p] = v.y;
        sbuf[(ch+2)*68+p] = v.z;
        sbuf[(ch+3)*68+p] = v.w;
    }
    __syncthreads();

    int cc = t & 15, pg = t >> 4;
    int cb = 4*cc, pb = 4*pg;

    float a[4][4];
    #pragma unroll
    for (int x = 0; x < 4; x++)
        #pragma unroll
        for (int y = 0; y < 4; y++) a[x][y] = 0.f;

    #pragma unroll 8
    for (int c = 0; c < 64; c++) {
        float4 w  = *(const float4*)&g_W2T[c*64 + cb];
        float4 xv = *(const float4*)&sbuf[c*68 + pb];
        float wc[4] = {w.x,w.y,w.z,w.w};
        float xp[4] = {xv.x,xv.y,xv.z,xv.w};
        #pragma unroll
        for (int ch = 0; ch < 4; ch++)
            #pragma unroll
            for (int pp = 0; pp < 4; pp++)
                a[ch][pp] = fmaf(wc[ch], xp[pp], a[ch][pp]);
    }
    __syncthreads();   // done reading sbuf, reuse as output stage

    float4 t2v = *(const float4*)&g_t2[cb];
    float tb[4] = {t2v.x, t2v.y, t2v.z, t2v.w};
    #pragma unroll
    for (int pp = 0; pp < 4; pp++) {
        float4 fv = *(const float4*)&g_f[(base + pb + pp)*64 + cb];
        float fr[4] = {fv.x, fv.y, fv.z, fv.w};
        #pragma unroll
        for (int ch = 0; ch < 4; ch++)
            sbuf[(cb+ch)*68 + pb + pp] = lrelu(a[ch][pp] + tb[ch] + fr[ch]);
    }
    __syncthreads();

    int cO = t >> 2, q = t & 3;
    #pragma unroll
    for (int i = 0; i < 4; i++) {
        float4 vq = *(const float4*)&sbuf[cO*68 + q*16 + 4*i];
        *(float4*)&out[((size_t)(b*64 + cO))*NPT + n0 + q*16 + 4*i] = vq;
    }
}

extern "C" void kernel_launch(void* const* d_in, const int* in_sizes, int n_in,
                              void* d_out, int out_size)
{
    const float* feature = (const float*)d_in[0];
    const float* xyz     = (const float*)d_in[1];
    const float* W1      = (const float*)d_in[2];
    const float* bn1     = (const float*)d_in[3];
    const float* Wq      = (const float*)d_in[4];
    const float* bq      = (const float*)d_in[5];
    const float* Wk      = (const float*)d_in[6];
    const float* bk      = (const float*)d_in[7];
    const float* Wv      = (const float*)d_in[8];
    const float* bv      = (const float*)d_in[9];
    const float* Wp1     = (const float*)d_in[10];
    const float* bnp1    = (const float*)d_in[11];
    const float* Wp2     = (const float*)d_in[12];
    const float* bp2     = (const float*)d_in[13];
    const float* bnw0    = (const float*)d_in[14];
    const float* Ww1     = (const float*)d_in[15];
    const float* bnw1    = (const float*)d_in[16];
    const float* Ww2     = (const float*)d_in[17];
    const float* bw2     = (const float*)d_in[18];
    const float* bn_mid  = (const float*)d_in[19];
    const float* W2      = (const float*)d_in[20];
    const float* bn2     = (const float*)d_in[21];
    const int*   nidx    = (const int*)d_in[22];
    float* out = (float*)d_out;

    k_prep<<<64, 64>>>(W1, bn1, Wq, bq, Wk, bk, Wv, bv, Wp1, bnp1, Wp2, bp2,
                       bnw0, Ww1, bnw1, Ww2, bw2, bn_mid, W2, bn2);
    dim3 gf(NPT/64, BB);
    k_proj<<<gf, 256>>>(feature, xyz);
    k_attn<<<(BB*NPT)/WPB, 128>>>(nidx);
    k_out<<<gf, 256>>>(out);
}